// round 4
// baseline (speedup 1.0000x reference)
#include <cuda_runtime.h>
#include <cuda_bf16.h>
#include <math.h>

// ---------------------------------------------------------------------------
// Problem dims
// ---------------------------------------------------------------------------
#define C2d 32
#define C1d 64
#define Td 2048
#define AVGF 32
#define SEG 64
#define Md 2048
#define TKd 3
#define HAd 16
#define DHd 128

// scratch (no allocations allowed -> __device__ globals)
__device__ float g_altx[AVGF * Md];
__device__ float g_s[AVGF * Md];
__device__ float g_y[AVGF * Md];
__device__ float g_qkv[AVGF * 3 * Md];
__device__ float g_imv[AVGF * Md];
__device__ float g_h[AVGF * 4 * Md];

// ---------------------------------------------------------------------------
// Kernel 1: segment average   altx[i, c1*32+c2] = mean_t x[c2, c1, i*64+t]
// grid = C2*C1 blocks (one per (c2,c1) row of T), 256 threads
// ---------------------------------------------------------------------------
__global__ void avg_kernel(const float* __restrict__ x, float* __restrict__ altx) {
    int b = blockIdx.x;           // b = c2*64 + c1
    int c2 = b >> 6, c1 = b & 63;
    const float* row = x + (size_t)b * Td;
    __shared__ float ssum[AVGF];
    int tid = threadIdx.x;
    if (tid < AVGF) ssum[tid] = 0.f;
    __syncthreads();
    // each thread sums 8 contiguous elements (all inside one 64-elem segment)
    float local = 0.f;
    int base = tid * 8;
#pragma unroll
    for (int m = 0; m < 8; m++) local += row[base + m];
    atomicAdd(&ssum[tid >> 3], local);
    __syncthreads();
    if (tid < AVGF)
        altx[tid * Md + c1 * 32 + c2] = ssum[tid] * (1.0f / 64.0f);
}

// ---------------------------------------------------------------------------
// Generic skinny GEMM:  OUT[32, N] = IN[32, K] @ W[N, K]^T  (+ epilogues)
// BK widened to 32: fewer __syncthreads barriers, 2x in-flight LDG bytes per
// stage (MLP ~16 on the B-tile loads) to hide DRAM latency at ~1 block/SM.
// ---------------------------------------------------------------------------
#define F_BIAS 1
#define F_RES  2
#define F_GELU 4
#define F_SIN  8

template<int BN, int TM, int TN, int FLAGS>
__global__ void __launch_bounds__(128, 1)
gemm32(const float* __restrict__ IN, const float* __restrict__ W,
       const float* __restrict__ bias, const float* __restrict__ resid,
       float* __restrict__ OUT, int N, int K)
{
    constexpr int BM = 32, BK = 32;
    constexpr int CT = BN / TN;
    constexpr int RT = BM / TM;
    constexpr int THREADS = CT * RT;

    __shared__ float As[BK][BM + 4];
    __shared__ float Bs[BK][BN + 4];

    const int tid = threadIdx.x;
    const int tx = tid % CT;
    const int ty = tid / CT;
    const int n0 = blockIdx.x * BN;

    float acc[TM][TN];
#pragma unroll
    for (int m = 0; m < TM; m++)
#pragma unroll
        for (int n = 0; n < TN; n++) acc[m][n] = 0.f;

    for (int k0 = 0; k0 < K; k0 += BK) {
        // load A tile [32 x BK] (vectorized, transpose into As[k][row])
#pragma unroll
        for (int t = tid; t < (BM * BK) / 4; t += THREADS) {
            int row = t >> 3;
            int kq = (t & 7) * 4;
            float4 v = *(const float4*)&IN[row * K + k0 + kq];
            As[kq + 0][row] = v.x; As[kq + 1][row] = v.y;
            As[kq + 2][row] = v.z; As[kq + 3][row] = v.w;
        }
        // load B tile [BN x BK] (coalesced over k, transpose into Bs[k][n])
#pragma unroll
        for (int t = tid; t < (BN * BK) / 4; t += THREADS) {
            int n = t >> 3;
            int kq = (t & 7) * 4;
            float4 v = *(const float4*)&W[(size_t)(n0 + n) * K + k0 + kq];
            Bs[kq + 0][n] = v.x; Bs[kq + 1][n] = v.y;
            Bs[kq + 2][n] = v.z; Bs[kq + 3][n] = v.w;
        }
        __syncthreads();

#pragma unroll
        for (int kk = 0; kk < BK; kk++) {
            float a[TM], b[TN];
            if constexpr (TM == 2) {
                float2 av = *(const float2*)&As[kk][ty * 2];
                a[0] = av.x; a[1] = av.y;
            } else {
                a[0] = As[kk][ty];
            }
            if constexpr (TN == 4) {
                float4 bv = *(const float4*)&Bs[kk][tx * 4];
                b[0] = bv.x; b[1] = bv.y; b[2] = bv.z; b[3] = bv.w;
            } else {
                float2 bv = *(const float2*)&Bs[kk][tx * 2];
                b[0] = bv.x; b[1] = bv.y;
            }
#pragma unroll
            for (int m = 0; m < TM; m++)
#pragma unroll
                for (int n = 0; n < TN; n++)
                    acc[m][n] = fmaf(a[m], b[n], acc[m][n]);
        }
        __syncthreads();
    }

    // epilogue
#pragma unroll
    for (int m = 0; m < TM; m++) {
        int r = ty * TM + m;
#pragma unroll
        for (int n = 0; n < TN; n++) {
            int c = n0 + tx * TN + n;
            float v = acc[m][n];
            if constexpr (FLAGS & F_BIAS) v += bias[c];
            if constexpr (FLAGS & F_SIN) {
                int e = c & ~1;
                float ang = (float)r * powf(10000.0f, -(float)e * (1.0f / 1024.0f));
                v += (c & 1) ? cosf(ang) : sinf(ang);
            }
            if constexpr (FLAGS & F_RES) v += resid[r * N + c];
            if constexpr (FLAGS & F_GELU)
                v = 0.5f * v * (1.0f + erff(v * 0.70710678118654752f));
            OUT[r * N + c] = v;
        }
    }
}

// ---------------------------------------------------------------------------
// LayerNorm (one block per row of 2048)
// ---------------------------------------------------------------------------
__device__ __forceinline__ float block_sum(float v, float* sh) {
#pragma unroll
    for (int o = 16; o; o >>= 1) v += __shfl_xor_sync(0xFFFFFFFFu, v, o);
    int w = threadIdx.x >> 5;
    if ((threadIdx.x & 31) == 0) sh[w] = v;
    __syncthreads();
    float r = 0.f;
    if (threadIdx.x < 8) r = sh[threadIdx.x];
    if (threadIdx.x < 32) {
#pragma unroll
        for (int o = 4; o; o >>= 1) r += __shfl_xor_sync(0xFFFFFFFFu, r, o);
    }
    if (threadIdx.x == 0) sh[0] = r;
    __syncthreads();
    float out = sh[0];
    __syncthreads();
    return out;
}

template<bool RESID>
__global__ void ln_kernel(const float* __restrict__ in, float* __restrict__ out,
                          const float* __restrict__ g, const float* __restrict__ bp) {
    __shared__ float sh[8];
    int row = blockIdx.x, tid = threadIdx.x;
    const float* p = in + row * Md;
    float v[8];
    float s = 0.f;
#pragma unroll
    for (int j = 0; j < 8; j++) { v[j] = p[tid + j * 256]; s += v[j]; }
    float mean = block_sum(s, sh) * (1.0f / (float)Md);
    float sq = 0.f;
#pragma unroll
    for (int j = 0; j < 8; j++) { float d = v[j] - mean; sq += d * d; }
    float var = block_sum(sq, sh) * (1.0f / (float)Md);
    float rstd = rsqrtf(var + 1e-5f);
#pragma unroll
    for (int j = 0; j < 8; j++) {
        int c = tid + j * 256;
        float o = (v[j] - mean) * rstd * g[c] + bp[c];
        if (RESID) o += v[j];
        out[row * Md + c] = o;
    }
}

// ---------------------------------------------------------------------------
// Scalar attention + serial cumsum over the 32 tokens.
// qkv layout: [32, 3*2048], q at h*128+d, k at +2048, v at +4096
// grid = 16 heads, 128 threads (= DH)
// ---------------------------------------------------------------------------
__global__ void attn_kernel(const float* __restrict__ qkv, float* __restrict__ imv) {
    __shared__ float red[4];
    int h = blockIdx.x;
    int d = threadIdx.x;
    const float inv = 0.088388347648318447f; // 1/sqrt(128)
    float run = 0.f;
    for (int i = 0; i < AVGF; i++) {
        int base = i * (3 * Md) + h * DHd + d;
        float q = qkv[base];
        float k = qkv[base + Md];
        float v = qkv[base + 2 * Md];
        float p = q * k;
#pragma unroll
        for (int o = 16; o; o >>= 1) p += __shfl_xor_sync(0xFFFFFFFFu, p, o);
        if ((d & 31) == 0) red[d >> 5] = p;
        __syncthreads();
        float rsa = (red[0] + red[1] + red[2] + red[3]) * inv;
        run += rsa * v;
        imv[i * Md + h * DHd + d] = run;
        __syncthreads();
    }
}

// ---------------------------------------------------------------------------
// launch
// ---------------------------------------------------------------------------
extern "C" void kernel_launch(void* const* d_in, const int* in_sizes, int n_in,
                              void* d_out, int out_size) {
    const float* x      = (const float*)d_in[0];
    const float* weight = (const float*)d_in[1];
    const float* Wqkv   = (const float*)d_in[2];
    const float* Wo     = (const float*)d_in[3];
    const float* ln1_g  = (const float*)d_in[4];
    const float* ln1_b  = (const float*)d_in[5];
    const float* ln2_g  = (const float*)d_in[6];
    const float* ln2_b  = (const float*)d_in[7];
    const float* fc1_w  = (const float*)d_in[8];
    const float* fc1_b  = (const float*)d_in[9];
    const float* fc2_w  = (const float*)d_in[10];
    const float* fc2_b  = (const float*)d_in[11];
    float* out = (float*)d_out;

    float *altx, *s, *y, *qkv, *imv, *hbuf;
    cudaGetSymbolAddress((void**)&altx, g_altx);
    cudaGetSymbolAddress((void**)&s,    g_s);
    cudaGetSymbolAddress((void**)&y,    g_y);
    cudaGetSymbolAddress((void**)&qkv,  g_qkv);
    cudaGetSymbolAddress((void**)&imv,  g_imv);
    cudaGetSymbolAddress((void**)&hbuf, g_h);

    // 1) segment average
    avg_kernel<<<C2d * C1d, 256>>>(x, altx);

    // 2) s = altx @ weight^T + sinusoidal bias     (N=2048, K=2048)
    gemm32<16, 2, 2, F_SIN><<<Md / 16, 128>>>(altx, weight, nullptr, nullptr, s, Md, Md);

    for (int a = 0; a < TKd; a++) {
        // y = LN1(s)
        ln_kernel<false><<<AVGF, 256>>>(s, y, ln1_g, ln1_b);

        // qkv = y @ Wqkv[a]^T      (N=6144, K=2048)
        gemm32<32, 2, 4, 0><<<(3 * Md) / 32, 128>>>(
            y, Wqkv + (size_t)a * 3 * Md * Md, nullptr, nullptr, qkv, 3 * Md, Md);

        // scalar attention + cumsum
        attn_kernel<<<HAd, DHd>>>(qkv, imv);

        // s = imv @ Wo[a]^T + s    (N=2048, K=2048)
        gemm32<16, 2, 2, F_RES><<<Md / 16, 128>>>(
            imv, Wo + (size_t)a * Md * Md, nullptr, s, s, Md, Md);

        // s = LN2(s) + s
        ln_kernel<true><<<AVGF, 256>>>(s, s, ln2_g, ln2_b);

        // h = gelu(s @ fc1^T + b)  (N=8192, K=2048)
        gemm32<32, 2, 4, F_BIAS | F_GELU><<<(4 * Md) / 32, 128>>>(
            s, fc1_w, fc1_b, nullptr, hbuf, 4 * Md, Md);

        // s = h @ fc2^T + b        (N=2048, K=8192); last iter writes d_out
        float* dst = (a == TKd - 1) ? out : s;
        gemm32<16, 2, 2, F_BIAS><<<Md / 16, 128>>>(
            hbuf, fc2_w, fc2_b, nullptr, dst, Md, 4 * Md);
    }
}

// round 5
// speedup vs baseline: 2.2805x; 2.2805x over previous
#include <cuda_runtime.h>
#include <cuda_bf16.h>
#include <math.h>

// ---------------------------------------------------------------------------
// Problem dims
// ---------------------------------------------------------------------------
#define C2d 32
#define C1d 64
#define Td 2048
#define AVGF 32
#define SEG 64
#define Md 2048
#define TKd 3
#define HAd 16
#define DHd 128

// scratch (no allocations allowed -> __device__ globals)
__device__ float g_altx[AVGF * Md];
__device__ float g_s[AVGF * Md];
__device__ float g_y[AVGF * Md];
__device__ float g_qkv[AVGF * 3 * Md];
__device__ float g_imv[AVGF * Md];
__device__ float g_h[AVGF * 4 * Md];
// split-K partial buffer: max = SPLITK(8) * 32 * 8192 = 2,097,152 floats (8 MB)
__device__ float g_part[2097152];

#define F_BIAS 1
#define F_RES  2
#define F_GELU 4
#define F_SIN  8

// ---------------------------------------------------------------------------
// Kernel 1: segment average   altx[i, c1*32+c2] = mean_t x[c2, c1, i*64+t]
// ---------------------------------------------------------------------------
__global__ void avg_kernel(const float* __restrict__ x, float* __restrict__ altx) {
    int b = blockIdx.x;           // b = c2*64 + c1
    int c2 = b >> 6, c1 = b & 63;
    const float* row = x + (size_t)b * Td;
    __shared__ float ssum[AVGF];
    int tid = threadIdx.x;
    if (tid < AVGF) ssum[tid] = 0.f;
    __syncthreads();
    float local = 0.f;
    int base = tid * 8;
#pragma unroll
    for (int m = 0; m < 8; m++) local += row[base + m];
    atomicAdd(&ssum[tid >> 3], local);
    __syncthreads();
    if (tid < AVGF)
        altx[tid * Md + c1 * 32 + c2] = ssum[tid] * (1.0f / 64.0f);
}

// ---------------------------------------------------------------------------
// Split-K skinny GEMM: PART[ky, 32, N] += IN[32, kslice] @ W[N, kslice]^T
// BM=32, BN=32, BK=32, TM=2, TN=4, 128 threads, double-buffered smem.
// ---------------------------------------------------------------------------
template<int SPLITK>
__global__ void __launch_bounds__(128, 1)
gemm32_part(const float* __restrict__ IN, const float* __restrict__ W,
            float* __restrict__ PART, int N, int K)
{
    constexpr int BM = 32, BK = 32, BN = 32, TM = 2, TN = 4;
    constexpr int CT = BN / TN;   // 8

    __shared__ float As[2][BK][BM + 4];
    __shared__ float Bs[2][BK][BN + 4];

    const int tid = threadIdx.x;
    const int tx = tid % CT;
    const int ty = tid / CT;
    const int n0 = blockIdx.x * BN;
    const int Ks = K / SPLITK;
    const int kbase = blockIdx.y * Ks;
    const int nIter = Ks / BK;

    float4 aR[2], bR[2];

    // ---- prologue: load tile 0 ----
#pragma unroll
    for (int j = 0; j < 2; j++) {
        int t = tid + j * 128;
        int row = t >> 3, kq = (t & 7) * 4;
        aR[j] = *(const float4*)&IN[row * K + kbase + kq];
        bR[j] = *(const float4*)&W[(size_t)(n0 + row) * K + kbase + kq];
    }
#pragma unroll
    for (int j = 0; j < 2; j++) {
        int t = tid + j * 128;
        int row = t >> 3, kq = (t & 7) * 4;
        As[0][kq + 0][row] = aR[j].x; As[0][kq + 1][row] = aR[j].y;
        As[0][kq + 2][row] = aR[j].z; As[0][kq + 3][row] = aR[j].w;
        Bs[0][kq + 0][row] = bR[j].x; Bs[0][kq + 1][row] = bR[j].y;
        Bs[0][kq + 2][row] = bR[j].z; Bs[0][kq + 3][row] = bR[j].w;
    }
    __syncthreads();

    float acc[TM][TN];
#pragma unroll
    for (int m = 0; m < TM; m++)
#pragma unroll
        for (int n = 0; n < TN; n++) acc[m][n] = 0.f;

    int buf = 0;
    for (int i = 0; i < nIter; i++) {
        // issue next tile's global loads early (latency overlaps compute)
        if (i + 1 < nIter) {
            int k0 = kbase + (i + 1) * BK;
#pragma unroll
            for (int j = 0; j < 2; j++) {
                int t = tid + j * 128;
                int row = t >> 3, kq = (t & 7) * 4;
                aR[j] = *(const float4*)&IN[row * K + k0 + kq];
                bR[j] = *(const float4*)&W[(size_t)(n0 + row) * K + k0 + kq];
            }
        }
        // compute current tile
#pragma unroll
        for (int kk = 0; kk < BK; kk++) {
            float2 av = *(const float2*)&As[buf][kk][ty * 2];
            float4 bv = *(const float4*)&Bs[buf][kk][tx * 4];
            acc[0][0] = fmaf(av.x, bv.x, acc[0][0]);
            acc[0][1] = fmaf(av.x, bv.y, acc[0][1]);
            acc[0][2] = fmaf(av.x, bv.z, acc[0][2]);
            acc[0][3] = fmaf(av.x, bv.w, acc[0][3]);
            acc[1][0] = fmaf(av.y, bv.x, acc[1][0]);
            acc[1][1] = fmaf(av.y, bv.y, acc[1][1]);
            acc[1][2] = fmaf(av.y, bv.z, acc[1][2]);
            acc[1][3] = fmaf(av.y, bv.w, acc[1][3]);
        }
        // stage next tile into the other buffer
        if (i + 1 < nIter) {
            int ob = buf ^ 1;
#pragma unroll
            for (int j = 0; j < 2; j++) {
                int t = tid + j * 128;
                int row = t >> 3, kq = (t & 7) * 4;
                As[ob][kq + 0][row] = aR[j].x; As[ob][kq + 1][row] = aR[j].y;
                As[ob][kq + 2][row] = aR[j].z; As[ob][kq + 3][row] = aR[j].w;
                Bs[ob][kq + 0][row] = bR[j].x; Bs[ob][kq + 1][row] = bR[j].y;
                Bs[ob][kq + 2][row] = bR[j].z; Bs[ob][kq + 3][row] = bR[j].w;
            }
        }
        __syncthreads();
        buf ^= 1;
    }

    // write partials (vectorized: tx*TN is contiguous 4)
#pragma unroll
    for (int m = 0; m < TM; m++) {
        int r = ty * TM + m;
        float4 v = make_float4(acc[m][0], acc[m][1], acc[m][2], acc[m][3]);
        *(float4*)&PART[((size_t)blockIdx.y * 32 + r) * N + n0 + tx * TN] = v;
    }
}

// ---------------------------------------------------------------------------
// Deterministic split-K reduction + fused epilogue.
// One thread per float4 of the [32, N] output.
// ---------------------------------------------------------------------------
template<int SPLITK, int FLAGS>
__global__ void reduce_ep(const float* __restrict__ PART, const float* __restrict__ bias,
                          const float* __restrict__ resid, float* __restrict__ OUT, int N)
{
    int idx = blockIdx.x * blockDim.x + threadIdx.x;
    int n4 = N >> 2;
    if (idx >= 32 * n4) return;
    int r = idx / n4;
    int c = (idx - r * n4) * 4;

    float o[4] = {0.f, 0.f, 0.f, 0.f};
#pragma unroll
    for (int p = 0; p < SPLITK; p++) {
        float4 v = *(const float4*)&PART[((size_t)p * 32 + r) * N + c];
        o[0] += v.x; o[1] += v.y; o[2] += v.z; o[3] += v.w;
    }
    if (FLAGS & F_BIAS) {
        float4 b = *(const float4*)&bias[c];
        o[0] += b.x; o[1] += b.y; o[2] += b.z; o[3] += b.w;
    }
    if (FLAGS & F_SIN) {
#pragma unroll
        for (int j = 0; j < 4; j++) {
            int cc = c + j;
            int e = cc & ~1;
            float ang = (float)r * powf(10000.0f, -(float)e * (1.0f / 1024.0f));
            o[j] += (cc & 1) ? cosf(ang) : sinf(ang);
        }
    }
    if (FLAGS & F_RES) {
        float4 v = *(const float4*)&resid[r * N + c];
        o[0] += v.x; o[1] += v.y; o[2] += v.z; o[3] += v.w;
    }
    if (FLAGS & F_GELU) {
#pragma unroll
        for (int j = 0; j < 4; j++)
            o[j] = 0.5f * o[j] * (1.0f + erff(o[j] * 0.70710678118654752f));
    }
    *(float4*)&OUT[r * N + c] = make_float4(o[0], o[1], o[2], o[3]);
}

// ---------------------------------------------------------------------------
// LayerNorm (one block per row of 2048)
// ---------------------------------------------------------------------------
__device__ __forceinline__ float block_sum(float v, float* sh) {
#pragma unroll
    for (int o = 16; o; o >>= 1) v += __shfl_xor_sync(0xFFFFFFFFu, v, o);
    int w = threadIdx.x >> 5;
    if ((threadIdx.x & 31) == 0) sh[w] = v;
    __syncthreads();
    float r = 0.f;
    if (threadIdx.x < 8) r = sh[threadIdx.x];
    if (threadIdx.x < 32) {
#pragma unroll
        for (int o = 4; o; o >>= 1) r += __shfl_xor_sync(0xFFFFFFFFu, r, o);
    }
    if (threadIdx.x == 0) sh[0] = r;
    __syncthreads();
    float out = sh[0];
    __syncthreads();
    return out;
}

template<bool RESID>
__global__ void ln_kernel(const float* __restrict__ in, float* __restrict__ out,
                          const float* __restrict__ g, const float* __restrict__ bp) {
    __shared__ float sh[8];
    int row = blockIdx.x, tid = threadIdx.x;
    const float* p = in + row * Md;
    float v[8];
    float s = 0.f;
#pragma unroll
    for (int j = 0; j < 8; j++) { v[j] = p[tid + j * 256]; s += v[j]; }
    float mean = block_sum(s, sh) * (1.0f / (float)Md);
    float sq = 0.f;
#pragma unroll
    for (int j = 0; j < 8; j++) { float d = v[j] - mean; sq += d * d; }
    float var = block_sum(sq, sh) * (1.0f / (float)Md);
    float rstd = rsqrtf(var + 1e-5f);
#pragma unroll
    for (int j = 0; j < 8; j++) {
        int c = tid + j * 256;
        float o = (v[j] - mean) * rstd * g[c] + bp[c];
        if (RESID) o += v[j];
        out[row * Md + c] = o;
    }
}

// ---------------------------------------------------------------------------
// Scalar attention + serial cumsum over the 32 tokens.
// ---------------------------------------------------------------------------
__global__ void attn_kernel(const float* __restrict__ qkv, float* __restrict__ imv) {
    __shared__ float red[4];
    int h = blockIdx.x;
    int d = threadIdx.x;
    const float inv = 0.088388347648318447f; // 1/sqrt(128)
    float run = 0.f;
    for (int i = 0; i < AVGF; i++) {
        int base = i * (3 * Md) + h * DHd + d;
        float q = qkv[base];
        float k = qkv[base + Md];
        float v = qkv[base + 2 * Md];
        float p = q * k;
#pragma unroll
        for (int o = 16; o; o >>= 1) p += __shfl_xor_sync(0xFFFFFFFFu, p, o);
        if ((d & 31) == 0) red[d >> 5] = p;
        __syncthreads();
        float rsa = (red[0] + red[1] + red[2] + red[3]) * inv;
        run += rsa * v;
        imv[i * Md + h * DHd + d] = run;
        __syncthreads();
    }
}

// ---------------------------------------------------------------------------
// launch
// ---------------------------------------------------------------------------
extern "C" void kernel_launch(void* const* d_in, const int* in_sizes, int n_in,
                              void* d_out, int out_size) {
    const float* x      = (const float*)d_in[0];
    const float* weight = (const float*)d_in[1];
    const float* Wqkv   = (const float*)d_in[2];
    const float* Wo     = (const float*)d_in[3];
    const float* ln1_g  = (const float*)d_in[4];
    const float* ln1_b  = (const float*)d_in[5];
    const float* ln2_g  = (const float*)d_in[6];
    const float* ln2_b  = (const float*)d_in[7];
    const float* fc1_w  = (const float*)d_in[8];
    const float* fc1_b  = (const float*)d_in[9];
    const float* fc2_w  = (const float*)d_in[10];
    const float* fc2_b  = (const float*)d_in[11];
    float* out = (float*)d_out;

    float *altx, *s, *y, *qkv, *imv, *hbuf, *part;
    cudaGetSymbolAddress((void**)&altx, g_altx);
    cudaGetSymbolAddress((void**)&s,    g_s);
    cudaGetSymbolAddress((void**)&y,    g_y);
    cudaGetSymbolAddress((void**)&qkv,  g_qkv);
    cudaGetSymbolAddress((void**)&imv,  g_imv);
    cudaGetSymbolAddress((void**)&hbuf, g_h);
    cudaGetSymbolAddress((void**)&part, g_part);

    // reduce grids: one thread per float4 of [32, N]
    const int RT_ = 128;
    auto rgrid = [](int N) { return (32 * (N / 4) + 127) / 128; };

    // 1) segment average
    avg_kernel<<<C2d * C1d, 256>>>(x, altx);

    // 2) s = altx @ weight^T + sinusoidal bias     (N=2048, K=2048, splitK=16)
    gemm32_part<16><<<dim3(Md / 32, 16), 128>>>(altx, weight, part, Md, Md);
    reduce_ep<16, F_SIN><<<rgrid(Md), RT_>>>(part, nullptr, nullptr, s, Md);

    for (int a = 0; a < TKd; a++) {
        // y = LN1(s)
        ln_kernel<false><<<AVGF, 256>>>(s, y, ln1_g, ln1_b);

        // qkv = y @ Wqkv[a]^T      (N=6144, K=2048, splitK=8)
        gemm32_part<8><<<dim3((3 * Md) / 32, 8), 128>>>(
            y, Wqkv + (size_t)a * 3 * Md * Md, part, 3 * Md, Md);
        reduce_ep<8, 0><<<rgrid(3 * Md), RT_>>>(part, nullptr, nullptr, qkv, 3 * Md);

        // scalar attention + cumsum
        attn_kernel<<<HAd, DHd>>>(qkv, imv);

        // s = imv @ Wo[a]^T + s    (N=2048, K=2048, splitK=16)
        gemm32_part<16><<<dim3(Md / 32, 16), 128>>>(
            imv, Wo + (size_t)a * Md * Md, part, Md, Md);
        reduce_ep<16, F_RES><<<rgrid(Md), RT_>>>(part, nullptr, s, s, Md);

        // s = LN2(s) + s
        ln_kernel<true><<<AVGF, 256>>>(s, s, ln2_g, ln2_b);

        // h = gelu(s @ fc1^T + b)  (N=8192, K=2048, splitK=8)
        gemm32_part<8><<<dim3((4 * Md) / 32, 8), 128>>>(s, fc1_w, part, 4 * Md, Md);
        reduce_ep<8, F_BIAS | F_GELU><<<rgrid(4 * Md), RT_>>>(
            part, fc1_b, nullptr, hbuf, 4 * Md);

        // s = h @ fc2^T + b        (N=2048, K=8192, splitK=16); last iter -> d_out
        float* dst = (a == TKd - 1) ? out : s;
        gemm32_part<16><<<dim3(Md / 32, 16), 128>>>(hbuf, fc2_w, part, Md, 4 * Md);
        reduce_ep<16, F_BIAS><<<rgrid(Md), RT_>>>(part, fc2_b, nullptr, dst, Md);
    }
}

// round 6
// speedup vs baseline: 2.5877x; 1.1347x over previous
#include <cuda_runtime.h>
#include <cuda_bf16.h>
#include <math.h>

// ---------------------------------------------------------------------------
// Problem dims
// ---------------------------------------------------------------------------
#define C2d 32
#define C1d 64
#define Td 2048
#define AVGF 32
#define SEG 64
#define Md 2048
#define TKd 3
#define HAd 16
#define DHd 128

// scratch (no allocations allowed -> __device__ globals)
__device__ float g_altx[AVGF * Md];
__device__ float g_s[AVGF * Md];
__device__ float g_y[AVGF * Md];
__device__ float g_qkv[AVGF * 3 * Md];
__device__ float g_imv[AVGF * Md];
__device__ float g_h[AVGF * 4 * Md];
// split-K partial buffer: max = 4 * 32 * 8192 = 1,048,576 floats (4 MB)
__device__ float g_part[1100000];

#define F_BIAS 1
#define F_RES  2
#define F_GELU 4
#define F_SIN  8

// ---------------------------------------------------------------------------
// helpers
// ---------------------------------------------------------------------------
__device__ __forceinline__ unsigned f2tf32(float f) {
    unsigned u;
    asm("cvt.rna.tf32.f32 %0, %1;" : "=r"(u) : "f"(f));
    return u;
}

__device__ __forceinline__ void mma_tf32(float c[4], unsigned a0, unsigned a1,
                                         unsigned a2, unsigned a3,
                                         unsigned b0, unsigned b1) {
    asm volatile(
        "mma.sync.aligned.m16n8k8.row.col.f32.tf32.tf32.f32 "
        "{%0,%1,%2,%3}, {%4,%5,%6,%7}, {%8,%9}, {%0,%1,%2,%3};"
        : "+f"(c[0]), "+f"(c[1]), "+f"(c[2]), "+f"(c[3])
        : "r"(a0), "r"(a1), "r"(a2), "r"(a3), "r"(b0), "r"(b1));
}

// ---------------------------------------------------------------------------
// Kernel 1: segment average   altx[i, c1*32+c2] = mean_t x[c2, c1, i*64+t]
// ---------------------------------------------------------------------------
__global__ void avg_kernel(const float* __restrict__ x, float* __restrict__ altx) {
    int b = blockIdx.x;           // b = c2*64 + c1
    int c2 = b >> 6, c1 = b & 63;
    const float* row = x + (size_t)b * Td;
    __shared__ float ssum[AVGF];
    int tid = threadIdx.x;
    if (tid < AVGF) ssum[tid] = 0.f;
    __syncthreads();
    float local = 0.f;
    int base = tid * 8;
#pragma unroll
    for (int m = 0; m < 8; m++) local += row[base + m];
    atomicAdd(&ssum[tid >> 3], local);
    __syncthreads();
    if (tid < AVGF)
        altx[tid * Md + c1 * 32 + c2] = ssum[tid] * (1.0f / 64.0f);
}

// ---------------------------------------------------------------------------
// Split-K skinny GEMM on tensor cores (tf32 mma.m16n8k8):
//   PART[ky, 32, N] = IN[32, kslice] @ W[N, kslice]^T
// BM=32, BN=32, BK=32, 128 threads (4 warps, each computes a [16,16] quadrant)
// Double-buffered smem; values converted to tf32 at the STS.
// ---------------------------------------------------------------------------
template<int SPLITK>
__global__ void __launch_bounds__(128, 1)
gemm32_mma(const float* __restrict__ IN, const float* __restrict__ W,
           float* __restrict__ PART, int N, int K)
{
    constexpr int BK = 32, BN = 32;
    __shared__ unsigned As[2][BK][40];   // As[k][m], pad 40 -> conflict-free frags
    __shared__ unsigned Bs[2][BK][40];   // Bs[k][n]

    const int tid  = threadIdx.x;
    const int lane = tid & 31;
    const int warp = tid >> 5;
    const int gid  = lane >> 2;   // 0..7
    const int tig  = lane & 3;    // 0..3
    const int mr   = (warp >> 1) * 16;   // warp's m base
    const int nc   = (warp & 1) * 16;    // warp's n base

    const int n0    = blockIdx.x * BN;
    const int Ks    = K / SPLITK;
    const int kbase = blockIdx.y * Ks;
    const int nIter = Ks / BK;

    float4 aR[2], bR[2];

    // prologue: load tile 0
#pragma unroll
    for (int j = 0; j < 2; j++) {
        int t = tid + j * 128;
        int row = t >> 3, kq = (t & 7) * 4;
        aR[j] = *(const float4*)&IN[row * K + kbase + kq];
        bR[j] = *(const float4*)&W[(size_t)(n0 + row) * K + kbase + kq];
    }
#pragma unroll
    for (int j = 0; j < 2; j++) {
        int t = tid + j * 128;
        int row = t >> 3, kq = (t & 7) * 4;
        As[0][kq + 0][row] = f2tf32(aR[j].x); As[0][kq + 1][row] = f2tf32(aR[j].y);
        As[0][kq + 2][row] = f2tf32(aR[j].z); As[0][kq + 3][row] = f2tf32(aR[j].w);
        Bs[0][kq + 0][row] = f2tf32(bR[j].x); Bs[0][kq + 1][row] = f2tf32(bR[j].y);
        Bs[0][kq + 2][row] = f2tf32(bR[j].z); Bs[0][kq + 3][row] = f2tf32(bR[j].w);
    }
    __syncthreads();

    float c[2][4] = {{0.f, 0.f, 0.f, 0.f}, {0.f, 0.f, 0.f, 0.f}};

    int buf = 0;
    for (int i = 0; i < nIter; i++) {
        // issue next tile's global loads early
        if (i + 1 < nIter) {
            int k0 = kbase + (i + 1) * BK;
#pragma unroll
            for (int j = 0; j < 2; j++) {
                int t = tid + j * 128;
                int row = t >> 3, kq = (t & 7) * 4;
                aR[j] = *(const float4*)&IN[row * K + k0 + kq];
                bR[j] = *(const float4*)&W[(size_t)(n0 + row) * K + k0 + kq];
            }
        }
        // tensor-core compute on current tile: 4 k-steps of 8
#pragma unroll
        for (int ks = 0; ks < 4; ks++) {
            int k0 = ks * 8;
            unsigned a0 = As[buf][k0 + tig][mr + gid];
            unsigned a1 = As[buf][k0 + tig][mr + gid + 8];
            unsigned a2 = As[buf][k0 + tig + 4][mr + gid];
            unsigned a3 = As[buf][k0 + tig + 4][mr + gid + 8];
#pragma unroll
            for (int t = 0; t < 2; t++) {
                unsigned b0 = Bs[buf][k0 + tig][nc + t * 8 + gid];
                unsigned b1 = Bs[buf][k0 + tig + 4][nc + t * 8 + gid];
                mma_tf32(c[t], a0, a1, a2, a3, b0, b1);
            }
        }
        // stage next tile into the other buffer
        if (i + 1 < nIter) {
            int ob = buf ^ 1;
#pragma unroll
            for (int j = 0; j < 2; j++) {
                int t = tid + j * 128;
                int row = t >> 3, kq = (t & 7) * 4;
                As[ob][kq + 0][row] = f2tf32(aR[j].x); As[ob][kq + 1][row] = f2tf32(aR[j].y);
                As[ob][kq + 2][row] = f2tf32(aR[j].z); As[ob][kq + 3][row] = f2tf32(aR[j].w);
                Bs[ob][kq + 0][row] = f2tf32(bR[j].x); Bs[ob][kq + 1][row] = f2tf32(bR[j].y);
                Bs[ob][kq + 2][row] = f2tf32(bR[j].z); Bs[ob][kq + 3][row] = f2tf32(bR[j].w);
            }
        }
        __syncthreads();
        buf ^= 1;
    }

    // write partials: D frag rows gid/gid+8, cols 2*tig, 2*tig+1
    float* base = &PART[(size_t)blockIdx.y * 32 * N];
#pragma unroll
    for (int t = 0; t < 2; t++) {
        int col = n0 + nc + t * 8 + 2 * tig;
        *(float2*)&base[(mr + gid) * N + col]     = make_float2(c[t][0], c[t][1]);
        *(float2*)&base[(mr + gid + 8) * N + col] = make_float2(c[t][2], c[t][3]);
    }
}

// ---------------------------------------------------------------------------
// block-wide sum (256 threads)
// ---------------------------------------------------------------------------
__device__ __forceinline__ float block_sum(float v, float* sh) {
#pragma unroll
    for (int o = 16; o; o >>= 1) v += __shfl_xor_sync(0xFFFFFFFFu, v, o);
    int w = threadIdx.x >> 5;
    if ((threadIdx.x & 31) == 0) sh[w] = v;
    __syncthreads();
    float r = 0.f;
    if (threadIdx.x < 32) {
        r = (threadIdx.x < 8) ? sh[threadIdx.x] : 0.f;
#pragma unroll
        for (int o = 4; o; o >>= 1) r += __shfl_xor_sync(0xFFFFFFFFu, r, o);
    }
    if (threadIdx.x == 0) sh[0] = r;
    __syncthreads();
    float out = sh[0];
    __syncthreads();
    return out;
}

// ---------------------------------------------------------------------------
// Fused split-K reduce + epilogue + LayerNorm for N=2048.
// One block per row (32 blocks, 256 threads, 8 elems/thread).
// LNMODE: 0 = write OUT_s = v only
//         1 = write OUT_s = v  and  OUT_y = LN(v)*g+b          (ln1)
//         2 = write OUT_s = LN(v)*g+b + v                      (ln2 + residual)
// ---------------------------------------------------------------------------
template<int SPLITK, int FLAGS, int LNMODE>
__global__ void reduce_ln(const float* __restrict__ PART, const float* __restrict__ bias,
                          const float* __restrict__ resid, float* __restrict__ OUT_s,
                          float* __restrict__ OUT_y, const float* __restrict__ g,
                          const float* __restrict__ bp)
{
    __shared__ float sh[8];
    const int r = blockIdx.x, tid = threadIdx.x;
    const int c0 = tid * 8;

    float o[8] = {0.f, 0.f, 0.f, 0.f, 0.f, 0.f, 0.f, 0.f};
#pragma unroll
    for (int p = 0; p < SPLITK; p++) {
        const float* b = &PART[((size_t)p * 32 + r) * Md + c0];
        float4 x0 = *(const float4*)b;
        float4 x1 = *(const float4*)(b + 4);
        o[0] += x0.x; o[1] += x0.y; o[2] += x0.z; o[3] += x0.w;
        o[4] += x1.x; o[5] += x1.y; o[6] += x1.z; o[7] += x1.w;
    }
    if (FLAGS & F_BIAS) {
        float4 b0 = *(const float4*)&bias[c0];
        float4 b1 = *(const float4*)&bias[c0 + 4];
        o[0] += b0.x; o[1] += b0.y; o[2] += b0.z; o[3] += b0.w;
        o[4] += b1.x; o[5] += b1.y; o[6] += b1.z; o[7] += b1.w;
    }
    if (FLAGS & F_SIN) {
#pragma unroll
        for (int j = 0; j < 8; j++) {
            int cc = c0 + j;
            int e = cc & ~1;
            float ang = (float)r * powf(10000.0f, -(float)e * (1.0f / 1024.0f));
            o[j] += (cc & 1) ? cosf(ang) : sinf(ang);
        }
    }
    if (FLAGS & F_RES) {
        const float* b = &resid[r * Md + c0];
        float4 x0 = *(const float4*)b;
        float4 x1 = *(const float4*)(b + 4);
        o[0] += x0.x; o[1] += x0.y; o[2] += x0.z; o[3] += x0.w;
        o[4] += x1.x; o[5] += x1.y; o[6] += x1.z; o[7] += x1.w;
    }

    if (LNMODE == 0) {
#pragma unroll
        for (int j = 0; j < 4; j++) {}
        *(float4*)&OUT_s[r * Md + c0]     = make_float4(o[0], o[1], o[2], o[3]);
        *(float4*)&OUT_s[r * Md + c0 + 4] = make_float4(o[4], o[5], o[6], o[7]);
        return;
    }

    float s = 0.f;
#pragma unroll
    for (int j = 0; j < 8; j++) s += o[j];
    float mean = block_sum(s, sh) * (1.0f / (float)Md);
    float sq = 0.f;
#pragma unroll
    for (int j = 0; j < 8; j++) { float d = o[j] - mean; sq += d * d; }
    float var = block_sum(sq, sh) * (1.0f / (float)Md);
    float rstd = rsqrtf(var + 1e-5f);

    float yv[8];
#pragma unroll
    for (int j = 0; j < 8; j++)
        yv[j] = (o[j] - mean) * rstd * g[c0 + j] + bp[c0 + j];

    if (LNMODE == 1) {
        *(float4*)&OUT_s[r * Md + c0]     = make_float4(o[0], o[1], o[2], o[3]);
        *(float4*)&OUT_s[r * Md + c0 + 4] = make_float4(o[4], o[5], o[6], o[7]);
        *(float4*)&OUT_y[r * Md + c0]     = make_float4(yv[0], yv[1], yv[2], yv[3]);
        *(float4*)&OUT_y[r * Md + c0 + 4] = make_float4(yv[4], yv[5], yv[6], yv[7]);
    } else { // LNMODE == 2
#pragma unroll
        for (int j = 0; j < 8; j++) yv[j] += o[j];
        *(float4*)&OUT_s[r * Md + c0]     = make_float4(yv[0], yv[1], yv[2], yv[3]);
        *(float4*)&OUT_s[r * Md + c0 + 4] = make_float4(yv[4], yv[5], yv[6], yv[7]);
    }
}

// ---------------------------------------------------------------------------
// Elementwise split-K reduction (for N=6144 / N=8192) + optional bias/gelu
// ---------------------------------------------------------------------------
template<int SPLITK, int FLAGS>
__global__ void reduce_ep(const float* __restrict__ PART, const float* __restrict__ bias,
                          float* __restrict__ OUT, int N)
{
    int idx = blockIdx.x * blockDim.x + threadIdx.x;
    int n4 = N >> 2;
    if (idx >= 32 * n4) return;
    int r = idx / n4;
    int c = (idx - r * n4) * 4;

    float o[4] = {0.f, 0.f, 0.f, 0.f};
#pragma unroll
    for (int p = 0; p < SPLITK; p++) {
        float4 v = *(const float4*)&PART[((size_t)p * 32 + r) * N + c];
        o[0] += v.x; o[1] += v.y; o[2] += v.z; o[3] += v.w;
    }
    if (FLAGS & F_BIAS) {
        float4 b = *(const float4*)&bias[c];
        o[0] += b.x; o[1] += b.y; o[2] += b.z; o[3] += b.w;
    }
    if (FLAGS & F_GELU) {
#pragma unroll
        for (int j = 0; j < 4; j++)
            o[j] = 0.5f * o[j] * (1.0f + erff(o[j] * 0.70710678118654752f));
    }
    *(float4*)&OUT[r * N + c] = make_float4(o[0], o[1], o[2], o[3]);
}

// ---------------------------------------------------------------------------
// Scalar attention + serial cumsum over the 32 tokens.
// ---------------------------------------------------------------------------
__global__ void attn_kernel(const float* __restrict__ qkv, float* __restrict__ imv) {
    __shared__ float red[4];
    int h = blockIdx.x;
    int d = threadIdx.x;
    const float inv = 0.088388347648318447f; // 1/sqrt(128)
    float run = 0.f;
    for (int i = 0; i < AVGF; i++) {
        int base = i * (3 * Md) + h * DHd + d;
        float q = qkv[base];
        float k = qkv[base + Md];
        float v = qkv[base + 2 * Md];
        float p = q * k;
#pragma unroll
        for (int o = 16; o; o >>= 1) p += __shfl_xor_sync(0xFFFFFFFFu, p, o);
        if ((d & 31) == 0) red[d >> 5] = p;
        __syncthreads();
        float rsa = (red[0] + red[1] + red[2] + red[3]) * inv;
        run += rsa * v;
        imv[i * Md + h * DHd + d] = run;
        __syncthreads();
    }
}

// ---------------------------------------------------------------------------
// launch
// ---------------------------------------------------------------------------
extern "C" void kernel_launch(void* const* d_in, const int* in_sizes, int n_in,
                              void* d_out, int out_size) {
    const float* x      = (const float*)d_in[0];
    const float* weight = (const float*)d_in[1];
    const float* Wqkv   = (const float*)d_in[2];
    const float* Wo     = (const float*)d_in[3];
    const float* ln1_g  = (const float*)d_in[4];
    const float* ln1_b  = (const float*)d_in[5];
    const float* ln2_g  = (const float*)d_in[6];
    const float* ln2_b  = (const float*)d_in[7];
    const float* fc1_w  = (const float*)d_in[8];
    const float* fc1_b  = (const float*)d_in[9];
    const float* fc2_w  = (const float*)d_in[10];
    const float* fc2_b  = (const float*)d_in[11];
    float* out = (float*)d_out;

    float *altx, *s, *y, *qkv, *imv, *hbuf, *part;
    cudaGetSymbolAddress((void**)&altx, g_altx);
    cudaGetSymbolAddress((void**)&s,    g_s);
    cudaGetSymbolAddress((void**)&y,    g_y);
    cudaGetSymbolAddress((void**)&qkv,  g_qkv);
    cudaGetSymbolAddress((void**)&imv,  g_imv);
    cudaGetSymbolAddress((void**)&hbuf, g_h);
    cudaGetSymbolAddress((void**)&part, g_part);

    auto rgrid = [](int N) { return (32 * (N / 4) + 127) / 128; };

    // 1) segment average
    avg_kernel<<<C2d * C1d, 256>>>(x, altx);

    // 2) s = altx @ weight^T + sin bias; y = LN1(s)   (N=2048, K=2048, splitK=8)
    gemm32_mma<8><<<dim3(Md / 32, 8), 128>>>(altx, weight, part, Md, Md);
    reduce_ln<8, F_SIN, 1><<<AVGF, 256>>>(part, nullptr, nullptr, s, y, ln1_g, ln1_b);

    for (int a = 0; a < TKd; a++) {
        // qkv = y @ Wqkv[a]^T      (N=6144, K=2048, splitK=4)
        gemm32_mma<4><<<dim3((3 * Md) / 32, 4), 128>>>(
            y, Wqkv + (size_t)a * 3 * Md * Md, part, 3 * Md, Md);
        reduce_ep<4, 0><<<rgrid(3 * Md), 128>>>(part, nullptr, qkv, 3 * Md);

        // scalar attention + cumsum
        attn_kernel<<<HAd, DHd>>>(qkv, imv);

        // s' = imv @ Wo[a]^T + s;  s = LN2(s') + s'   (N=2048, K=2048, splitK=8)
        gemm32_mma<8><<<dim3(Md / 32, 8), 128>>>(
            imv, Wo + (size_t)a * Md * Md, part, Md, Md);
        reduce_ln<8, F_RES, 2><<<AVGF, 256>>>(part, nullptr, s, s, nullptr, ln2_g, ln2_b);

        // h = gelu(s @ fc1^T + b)  (N=8192, K=2048, splitK=4)
        gemm32_mma<4><<<dim3((4 * Md) / 32, 4), 128>>>(s, fc1_w, part, 4 * Md, Md);
        reduce_ep<4, F_BIAS | F_GELU><<<rgrid(4 * Md), 128>>>(part, fc1_b, hbuf, 4 * Md);

        // s = h @ fc2^T + b        (N=2048, K=8192, splitK=8)
        gemm32_mma<8><<<dim3(Md / 32, 8), 128>>>(hbuf, fc2_w, part, Md, 4 * Md);
        if (a < TKd - 1) {
            // fuse next block's LN1: write s and y
            reduce_ln<8, F_BIAS, 1><<<AVGF, 256>>>(part, fc2_b, nullptr, s, y,
                                                   ln1_g, ln1_b);
        } else {
            reduce_ln<8, F_BIAS, 0><<<AVGF, 256>>>(part, fc2_b, nullptr, out, nullptr,
                                                   nullptr, nullptr);
        }
    }
}

// round 7
// speedup vs baseline: 3.5629x; 1.3769x over previous
#include <cuda_runtime.h>
#include <cuda_bf16.h>
#include <math.h>

// ---------------------------------------------------------------------------
// Problem dims
// ---------------------------------------------------------------------------
#define C2d 32
#define C1d 64
#define Td 2048
#define AVGF 32
#define SEG 64
#define Md 2048
#define TKd 3
#define HAd 16
#define DHd 128

// scratch (no allocations allowed -> __device__ globals)
__device__ float g_altx[AVGF * Md];
__device__ float g_s[AVGF * Md];
__device__ float g_y[AVGF * Md];
__device__ float g_qkv[AVGF * 3 * Md];
__device__ float g_imv[AVGF * Md];
__device__ float g_h[AVGF * 4 * Md];
// split-K partial buffer: max = 32 * 32 * 2048 = 2,097,152 floats (8.4 MB)
__device__ float g_part[2100000];

#define F_BIAS 1
#define F_RES  2
#define F_GELU 4
#define F_SIN  8

// ---------------------------------------------------------------------------
// helpers: bf16 2-plane split (hi = rn(v), lo = rn(v - hi)); k-pairs packed
// into one 32-bit word (lo half = even k, hi half = odd k).
// ---------------------------------------------------------------------------
__device__ __forceinline__ void split2(float x0, float x1, unsigned& hi, unsigned& lo) {
    asm("cvt.rn.bf16x2.f32 %0, %1, %2;" : "=r"(hi) : "f"(x1), "f"(x0));
    float h0 = __uint_as_float(hi << 16);
    float h1 = __uint_as_float(hi & 0xFFFF0000u);
    float l0 = x0 - h0;
    float l1 = x1 - h1;
    asm("cvt.rn.bf16x2.f32 %0, %1, %2;" : "=r"(lo) : "f"(l1), "f"(l0));
}

__device__ __forceinline__ void mma_bf16(float c[4], unsigned a0, unsigned a1,
                                         unsigned a2, unsigned a3,
                                         unsigned b0, unsigned b1) {
    asm volatile(
        "mma.sync.aligned.m16n8k16.row.col.f32.bf16.bf16.f32 "
        "{%0,%1,%2,%3}, {%4,%5,%6,%7}, {%8,%9}, {%0,%1,%2,%3};"
        : "+f"(c[0]), "+f"(c[1]), "+f"(c[2]), "+f"(c[3])
        : "r"(a0), "r"(a1), "r"(a2), "r"(a3), "r"(b0), "r"(b1));
}

// ---------------------------------------------------------------------------
// Kernel 1: segment average   altx[i, c1*32+c2] = mean_t x[c2, c1, i*64+t]
// ---------------------------------------------------------------------------
__global__ void avg_kernel(const float* __restrict__ x, float* __restrict__ altx) {
    int b = blockIdx.x;           // b = c2*64 + c1
    int c2 = b >> 6, c1 = b & 63;
    const float* row = x + (size_t)b * Td;
    __shared__ float ssum[AVGF];
    int tid = threadIdx.x;
    if (tid < AVGF) ssum[tid] = 0.f;
    __syncthreads();
    float local = 0.f;
    int base = tid * 8;
#pragma unroll
    for (int m = 0; m < 8; m++) local += row[base + m];
    atomicAdd(&ssum[tid >> 3], local);
    __syncthreads();
    if (tid < AVGF)
        altx[tid * Md + c1 * 32 + c2] = ssum[tid] * (1.0f / 64.0f);
}

// ---------------------------------------------------------------------------
// Split-K skinny GEMM, bf16 2-plane emulation of fp32 on tensor cores:
//   PART[ky, 32, N] = IN[32, kslice] @ W[N, kslice]^T
// BM=32, BN=32, BK=32, 128 threads, 4 warps each computing a 16x16 quadrant.
// D = hi*hi + hi*lo + lo*hi  (m16n8k16 bf16 MMAs; lo*lo dropped, ~2^-15 err)
// smem word at [plane][kp][m] packs k=2kp (lo half) and k=2kp+1 (hi half).
// Pad 40 -> fragment loads are bank-conflict-free (bank = 8*kp + m).
// ---------------------------------------------------------------------------
template<int SPLITK>
__global__ void __launch_bounds__(128, 1)
gemm32_mma(const float* __restrict__ IN, const float* __restrict__ W,
           float* __restrict__ PART, int N, int K)
{
    __shared__ unsigned As[2][2][16][40];   // [buf][plane][kp][m]
    __shared__ unsigned Bs[2][2][16][40];   // [buf][plane][kp][n]

    const int tid  = threadIdx.x;
    const int lane = tid & 31;
    const int warp = tid >> 5;
    const int gid  = lane >> 2;   // 0..7
    const int tig  = lane & 3;    // 0..3
    const int mr   = (warp >> 1) * 16;   // warp's m base
    const int nc   = (warp & 1) * 16;    // warp's n base

    const int n0    = blockIdx.x * 32;
    const int Ks    = K / SPLITK;
    const int kbase = blockIdx.y * Ks;
    const int nIter = Ks / 32;

    float4 aR[2], bR[2];

    // per-thread (row, kq) map: 8 lanes cover one 128B row segment (coalesced)
    // t = tid + j*128; row = t>>3 (0..31), kq = (t&7)*4, kp0 = (t&7)*2

    // ---- prologue: load tile 0 ----
#pragma unroll
    for (int j = 0; j < 2; j++) {
        int t = tid + j * 128;
        int row = t >> 3, kq = (t & 7) * 4;
        aR[j] = *(const float4*)&IN[row * K + kbase + kq];
        bR[j] = *(const float4*)&W[(size_t)(n0 + row) * K + kbase + kq];
    }
#pragma unroll
    for (int j = 0; j < 2; j++) {
        int t = tid + j * 128;
        int row = t >> 3, kp0 = (t & 7) * 2;
        unsigned h, l;
        split2(aR[j].x, aR[j].y, h, l);
        As[0][0][kp0][row] = h;     As[0][1][kp0][row] = l;
        split2(aR[j].z, aR[j].w, h, l);
        As[0][0][kp0 + 1][row] = h; As[0][1][kp0 + 1][row] = l;
        split2(bR[j].x, bR[j].y, h, l);
        Bs[0][0][kp0][row] = h;     Bs[0][1][kp0][row] = l;
        split2(bR[j].z, bR[j].w, h, l);
        Bs[0][0][kp0 + 1][row] = h; Bs[0][1][kp0 + 1][row] = l;
    }
    __syncthreads();

    float c[2][4] = {{0.f, 0.f, 0.f, 0.f}, {0.f, 0.f, 0.f, 0.f}};

    int buf = 0;
    for (int i = 0; i < nIter; i++) {
        // issue next tile's global loads early (overlap with MMA)
        if (i + 1 < nIter) {
            int k0 = kbase + (i + 1) * 32;
#pragma unroll
            for (int j = 0; j < 2; j++) {
                int t = tid + j * 128;
                int row = t >> 3, kq = (t & 7) * 4;
                aR[j] = *(const float4*)&IN[row * K + k0 + kq];
                bR[j] = *(const float4*)&W[(size_t)(n0 + row) * K + k0 + kq];
            }
        }
        // tensor-core compute: 2 k16 steps, 3 plane-combos each
#pragma unroll
        for (int s = 0; s < 2; s++) {
            int kp = s * 8;
            unsigned ah0 = As[buf][0][kp + tig][mr + gid];
            unsigned ah1 = As[buf][0][kp + tig][mr + gid + 8];
            unsigned ah2 = As[buf][0][kp + tig + 4][mr + gid];
            unsigned ah3 = As[buf][0][kp + tig + 4][mr + gid + 8];
            unsigned al0 = As[buf][1][kp + tig][mr + gid];
            unsigned al1 = As[buf][1][kp + tig][mr + gid + 8];
            unsigned al2 = As[buf][1][kp + tig + 4][mr + gid];
            unsigned al3 = As[buf][1][kp + tig + 4][mr + gid + 8];
#pragma unroll
            for (int t = 0; t < 2; t++) {
                unsigned bh0 = Bs[buf][0][kp + tig][nc + t * 8 + gid];
                unsigned bh1 = Bs[buf][0][kp + tig + 4][nc + t * 8 + gid];
                unsigned bl0 = Bs[buf][1][kp + tig][nc + t * 8 + gid];
                unsigned bl1 = Bs[buf][1][kp + tig + 4][nc + t * 8 + gid];
                mma_bf16(c[t], ah0, ah1, ah2, ah3, bh0, bh1);
                mma_bf16(c[t], ah0, ah1, ah2, ah3, bl0, bl1);
                mma_bf16(c[t], al0, al1, al2, al3, bh0, bh1);
            }
        }
        // stage next tile into the other buffer
        if (i + 1 < nIter) {
            int ob = buf ^ 1;
#pragma unroll
            for (int j = 0; j < 2; j++) {
                int t = tid + j * 128;
                int row = t >> 3, kp0 = (t & 7) * 2;
                unsigned h, l;
                split2(aR[j].x, aR[j].y, h, l);
                As[ob][0][kp0][row] = h;     As[ob][1][kp0][row] = l;
                split2(aR[j].z, aR[j].w, h, l);
                As[ob][0][kp0 + 1][row] = h; As[ob][1][kp0 + 1][row] = l;
                split2(bR[j].x, bR[j].y, h, l);
                Bs[ob][0][kp0][row] = h;     Bs[ob][1][kp0][row] = l;
                split2(bR[j].z, bR[j].w, h, l);
                Bs[ob][0][kp0 + 1][row] = h; Bs[ob][1][kp0 + 1][row] = l;
            }
        }
        __syncthreads();
        buf ^= 1;
    }

    // write partials: D frag rows gid/gid+8, cols 2*tig, 2*tig+1
    float* base = &PART[(size_t)blockIdx.y * 32 * N];
#pragma unroll
    for (int t = 0; t < 2; t++) {
        int col = n0 + nc + t * 8 + 2 * tig;
        *(float2*)&base[(mr + gid) * N + col]     = make_float2(c[t][0], c[t][1]);
        *(float2*)&base[(mr + gid + 8) * N + col] = make_float2(c[t][2], c[t][3]);
    }
}

// ---------------------------------------------------------------------------
// block-wide sum (256 threads)
// ---------------------------------------------------------------------------
__device__ __forceinline__ float block_sum(float v, float* sh) {
#pragma unroll
    for (int o = 16; o; o >>= 1) v += __shfl_xor_sync(0xFFFFFFFFu, v, o);
    int w = threadIdx.x >> 5;
    if ((threadIdx.x & 31) == 0) sh[w] = v;
    __syncthreads();
    float r = 0.f;
    if (threadIdx.x < 32) {
        r = (threadIdx.x < 8) ? sh[threadIdx.x] : 0.f;
#pragma unroll
        for (int o = 4; o; o >>= 1) r += __shfl_xor_sync(0xFFFFFFFFu, r, o);
    }
    if (threadIdx.x == 0) sh[0] = r;
    __syncthreads();
    float out = sh[0];
    __syncthreads();
    return out;
}

// ---------------------------------------------------------------------------
// Fused split-K reduce + epilogue + LayerNorm for N=2048.
// One block per row (32 blocks, 256 threads, 8 elems/thread).
// LNMODE: 0 = write OUT_s = v only
//         1 = write OUT_s = v  and  OUT_y = LN(v)*g+b          (ln1)
//         2 = write OUT_s = LN(v)*g+b + v                      (ln2 + residual)
// ---------------------------------------------------------------------------
template<int SPLITK, int FLAGS, int LNMODE>
__global__ void reduce_ln(const float* __restrict__ PART, const float* __restrict__ bias,
                          const float* __restrict__ resid, float* __restrict__ OUT_s,
                          float* __restrict__ OUT_y, const float* __restrict__ g,
                          const float* __restrict__ bp)
{
    __shared__ float sh[8];
    const int r = blockIdx.x, tid = threadIdx.x;
    const int c0 = tid * 8;

    float o[8] = {0.f, 0.f, 0.f, 0.f, 0.f, 0.f, 0.f, 0.f};
#pragma unroll
    for (int p = 0; p < SPLITK; p++) {
        const float* b = &PART[((size_t)p * 32 + r) * Md + c0];
        float4 x0 = *(const float4*)b;
        float4 x1 = *(const float4*)(b + 4);
        o[0] += x0.x; o[1] += x0.y; o[2] += x0.z; o[3] += x0.w;
        o[4] += x1.x; o[5] += x1.y; o[6] += x1.z; o[7] += x1.w;
    }
    if (FLAGS & F_BIAS) {
        float4 b0 = *(const float4*)&bias[c0];
        float4 b1 = *(const float4*)&bias[c0 + 4];
        o[0] += b0.x; o[1] += b0.y; o[2] += b0.z; o[3] += b0.w;
        o[4] += b1.x; o[5] += b1.y; o[6] += b1.z; o[7] += b1.w;
    }
    if (FLAGS & F_SIN) {
#pragma unroll
        for (int j = 0; j < 8; j++) {
            int cc = c0 + j;
            int e = cc & ~1;
            float ang = (float)r * powf(10000.0f, -(float)e * (1.0f / 1024.0f));
            o[j] += (cc & 1) ? cosf(ang) : sinf(ang);
        }
    }
    if (FLAGS & F_RES) {
        const float* b = &resid[r * Md + c0];
        float4 x0 = *(const float4*)b;
        float4 x1 = *(const float4*)(b + 4);
        o[0] += x0.x; o[1] += x0.y; o[2] += x0.z; o[3] += x0.w;
        o[4] += x1.x; o[5] += x1.y; o[6] += x1.z; o[7] += x1.w;
    }

    if (LNMODE == 0) {
        *(float4*)&OUT_s[r * Md + c0]     = make_float4(o[0], o[1], o[2], o[3]);
        *(float4*)&OUT_s[r * Md + c0 + 4] = make_float4(o[4], o[5], o[6], o[7]);
        return;
    }

    float s = 0.f;
#pragma unroll
    for (int j = 0; j < 8; j++) s += o[j];
    float mean = block_sum(s, sh) * (1.0f / (float)Md);
    float sq = 0.f;
#pragma unroll
    for (int j = 0; j < 8; j++) { float d = o[j] - mean; sq += d * d; }
    float var = block_sum(sq, sh) * (1.0f / (float)Md);
    float rstd = rsqrtf(var + 1e-5f);

    float yv[8];
#pragma unroll
    for (int j = 0; j < 8; j++)
        yv[j] = (o[j] - mean) * rstd * g[c0 + j] + bp[c0 + j];

    if (LNMODE == 1) {
        *(float4*)&OUT_s[r * Md + c0]     = make_float4(o[0], o[1], o[2], o[3]);
        *(float4*)&OUT_s[r * Md + c0 + 4] = make_float4(o[4], o[5], o[6], o[7]);
        *(float4*)&OUT_y[r * Md + c0]     = make_float4(yv[0], yv[1], yv[2], yv[3]);
        *(float4*)&OUT_y[r * Md + c0 + 4] = make_float4(yv[4], yv[5], yv[6], yv[7]);
    } else { // LNMODE == 2
#pragma unroll
        for (int j = 0; j < 8; j++) yv[j] += o[j];
        *(float4*)&OUT_s[r * Md + c0]     = make_float4(yv[0], yv[1], yv[2], yv[3]);
        *(float4*)&OUT_s[r * Md + c0 + 4] = make_float4(yv[4], yv[5], yv[6], yv[7]);
    }
}

// ---------------------------------------------------------------------------
// Elementwise split-K reduction (for N=6144 / N=8192) + optional bias/gelu
// ---------------------------------------------------------------------------
template<int SPLITK, int FLAGS>
__global__ void reduce_ep(const float* __restrict__ PART, const float* __restrict__ bias,
                          float* __restrict__ OUT, int N)
{
    int idx = blockIdx.x * blockDim.x + threadIdx.x;
    int n4 = N >> 2;
    if (idx >= 32 * n4) return;
    int r = idx / n4;
    int c = (idx - r * n4) * 4;

    float o[4] = {0.f, 0.f, 0.f, 0.f};
#pragma unroll
    for (int p = 0; p < SPLITK; p++) {
        float4 v = *(const float4*)&PART[((size_t)p * 32 + r) * N + c];
        o[0] += v.x; o[1] += v.y; o[2] += v.z; o[3] += v.w;
    }
    if (FLAGS & F_BIAS) {
        float4 b = *(const float4*)&bias[c];
        o[0] += b.x; o[1] += b.y; o[2] += b.z; o[3] += b.w;
    }
    if (FLAGS & F_GELU) {
#pragma unroll
        for (int j = 0; j < 4; j++)
            o[j] = 0.5f * o[j] * (1.0f + erff(o[j] * 0.70710678118654752f));
    }
    *(float4*)&OUT[r * N + c] = make_float4(o[0], o[1], o[2], o[3]);
}

// ---------------------------------------------------------------------------
// Scalar attention + serial cumsum over the 32 tokens.
// ---------------------------------------------------------------------------
__global__ void attn_kernel(const float* __restrict__ qkv, float* __restrict__ imv) {
    __shared__ float red[4];
    int h = blockIdx.x;
    int d = threadIdx.x;
    const float inv = 0.088388347648318447f; // 1/sqrt(128)
    float run = 0.f;
    for (int i = 0; i < AVGF; i++) {
        int base = i * (3 * Md) + h * DHd + d;
        float q = qkv[base];
        float k = qkv[base + Md];
        float v = qkv[base + 2 * Md];
        float p = q * k;
#pragma unroll
        for (int o = 16; o; o >>= 1) p += __shfl_xor_sync(0xFFFFFFFFu, p, o);
        if ((d & 31) == 0) red[d >> 5] = p;
        __syncthreads();
        float rsa = (red[0] + red[1] + red[2] + red[3]) * inv;
        run += rsa * v;
        imv[i * Md + h * DHd + d] = run;
        __syncthreads();
    }
}

// ---------------------------------------------------------------------------
// launch
// ---------------------------------------------------------------------------
extern "C" void kernel_launch(void* const* d_in, const int* in_sizes, int n_in,
                              void* d_out, int out_size) {
    const float* x      = (const float*)d_in[0];
    const float* weight = (const float*)d_in[1];
    const float* Wqkv   = (const float*)d_in[2];
    const float* Wo     = (const float*)d_in[3];
    const float* ln1_g  = (const float*)d_in[4];
    const float* ln1_b  = (const float*)d_in[5];
    const float* ln2_g  = (const float*)d_in[6];
    const float* ln2_b  = (const float*)d_in[7];
    const float* fc1_w  = (const float*)d_in[8];
    const float* fc1_b  = (const float*)d_in[9];
    const float* fc2_w  = (const float*)d_in[10];
    const float* fc2_b  = (const float*)d_in[11];
    float* out = (float*)d_out;

    float *altx, *s, *y, *qkv, *imv, *hbuf, *part;
    cudaGetSymbolAddress((void**)&altx, g_altx);
    cudaGetSymbolAddress((void**)&s,    g_s);
    cudaGetSymbolAddress((void**)&y,    g_y);
    cudaGetSymbolAddress((void**)&qkv,  g_qkv);
    cudaGetSymbolAddress((void**)&imv,  g_imv);
    cudaGetSymbolAddress((void**)&hbuf, g_h);
    cudaGetSymbolAddress((void**)&part, g_part);

    auto rgrid = [](int N) { return (32 * (N / 4) + 127) / 128; };

    // 1) segment average
    avg_kernel<<<C2d * C1d, 256>>>(x, altx);

    // 2) s = altx @ weight^T + sin bias; y = LN1(s)   (N=2048, K=2048, splitK=32)
    gemm32_mma<32><<<dim3(Md / 32, 32), 128>>>(altx, weight, part, Md, Md);
    reduce_ln<32, F_SIN, 1><<<AVGF, 256>>>(part, nullptr, nullptr, s, y, ln1_g, ln1_b);

    for (int a = 0; a < TKd; a++) {
        // qkv = y @ Wqkv[a]^T      (N=6144, K=2048, splitK=8 -> 1536 blocks)
        gemm32_mma<8><<<dim3((3 * Md) / 32, 8), 128>>>(
            y, Wqkv + (size_t)a * 3 * Md * Md, part, 3 * Md, Md);
        reduce_ep<8, 0><<<rgrid(3 * Md), 128>>>(part, nullptr, qkv, 3 * Md);

        // scalar attention + cumsum
        attn_kernel<<<HAd, DHd>>>(qkv, imv);

        // s' = imv @ Wo[a]^T + s;  s = LN2(s') + s'   (N=2048, K=2048, splitK=32)
        gemm32_mma<32><<<dim3(Md / 32, 32), 128>>>(
            imv, Wo + (size_t)a * Md * Md, part, Md, Md);
        reduce_ln<32, F_RES, 2><<<AVGF, 256>>>(part, nullptr, s, s, nullptr, ln2_g, ln2_b);

        // h = gelu(s @ fc1^T + b)  (N=8192, K=2048, splitK=8 -> 2048 blocks)
        gemm32_mma<8><<<dim3((4 * Md) / 32, 8), 128>>>(s, fc1_w, part, 4 * Md, Md);
        reduce_ep<8, F_BIAS | F_GELU><<<rgrid(4 * Md), 128>>>(part, fc1_b, hbuf, 4 * Md);

        // s = h @ fc2^T + b        (N=2048, K=8192, splitK=32 -> 2048 blocks)
        gemm32_mma<32><<<dim3(Md / 32, 32), 128>>>(hbuf, fc2_w, part, Md, 4 * Md);
        if (a < TKd - 1) {
            // fuse next block's LN1: write s and y
            reduce_ln<32, F_BIAS, 1><<<AVGF, 256>>>(part, fc2_b, nullptr, s, y,
                                                    ln1_g, ln1_b);
        } else {
            reduce_ln<32, F_BIAS, 0><<<AVGF, 256>>>(part, fc2_b, nullptr, out, nullptr,
                                                    nullptr, nullptr);
        }
    }
}

// round 8
// speedup vs baseline: 4.9423x; 1.3871x over previous
#include <cuda_runtime.h>
#include <cuda_bf16.h>
#include <math.h>

// ---------------------------------------------------------------------------
// Problem dims
// ---------------------------------------------------------------------------
#define C2d 32
#define C1d 64
#define Td 2048
#define AVGF 32
#define SEG 64
#define Md 2048
#define TKd 3
#define HAd 16
#define DHd 128

// scratch (no allocations allowed -> __device__ globals)
__device__ float g_altx[AVGF * Md];
__device__ float g_s[AVGF * Md];
__device__ float g_y[AVGF * Md];
__device__ float g_qkv[AVGF * 3 * Md];
__device__ float g_imv[AVGF * Md];
__device__ float g_h[AVGF * 4 * Md];
// split-K partial buffer: max = 8 * 32 * 8192 = 2,097,152 floats (8.4 MB)
__device__ float g_part[2100000];

#define F_BIAS 1
#define F_RES  2
#define F_GELU 4
#define F_SIN  8

// ---------------------------------------------------------------------------
// helpers: bf16 2-plane split (hi = rn(v), lo = rn(v - hi)); k-pairs packed
// into one 32-bit word (lo half = even k, hi half = odd k).
// ---------------------------------------------------------------------------
__device__ __forceinline__ void split2(float x0, float x1, unsigned& hi, unsigned& lo) {
    asm("cvt.rn.bf16x2.f32 %0, %1, %2;" : "=r"(hi) : "f"(x1), "f"(x0));
    float h0 = __uint_as_float(hi << 16);
    float h1 = __uint_as_float(hi & 0xFFFF0000u);
    float l0 = x0 - h0;
    float l1 = x1 - h1;
    asm("cvt.rn.bf16x2.f32 %0, %1, %2;" : "=r"(lo) : "f"(l1), "f"(l0));
}

__device__ __forceinline__ void mma_bf16(float c[4], unsigned a0, unsigned a1,
                                         unsigned a2, unsigned a3,
                                         unsigned b0, unsigned b1) {
    asm volatile(
        "mma.sync.aligned.m16n8k16.row.col.f32.bf16.bf16.f32 "
        "{%0,%1,%2,%3}, {%4,%5,%6,%7}, {%8,%9}, {%0,%1,%2,%3};"
        : "+f"(c[0]), "+f"(c[1]), "+f"(c[2]), "+f"(c[3])
        : "r"(a0), "r"(a1), "r"(a2), "r"(a3), "r"(b0), "r"(b1));
}

// ---------------------------------------------------------------------------
// Kernel 1: segment average   altx[i, c1*32+c2] = mean_t x[c2, c1, i*64+t]
// ---------------------------------------------------------------------------
__global__ void avg_kernel(const float* __restrict__ x, float* __restrict__ altx) {
    int b = blockIdx.x;           // b = c2*64 + c1
    int c2 = b >> 6, c1 = b & 63;
    const float* row = x + (size_t)b * Td;
    __shared__ float ssum[AVGF];
    int tid = threadIdx.x;
    if (tid < AVGF) ssum[tid] = 0.f;
    __syncthreads();
    float local = 0.f;
    int base = tid * 8;
#pragma unroll
    for (int m = 0; m < 8; m++) local += row[base + m];
    atomicAdd(&ssum[tid >> 3], local);
    __syncthreads();
    if (tid < AVGF)
        altx[tid * Md + c1 * 32 + c2] = ssum[tid] * (1.0f / 64.0f);
}

// ---------------------------------------------------------------------------
// Split-K skinny GEMM, bf16 2-plane emulation of fp32 on tensor cores:
//   PART[ky, 32, N] = IN[32, kslice] @ W[N, kslice]^T
// BM=32, BN=64, BK=32, 128 threads; warp w computes the 32 x [16w,16w+16)
// slice (2 m16 tiles x 2 n8 tiles, 3 plane-MMAs each = 12 MMA / k16-step).
// Staging: each thread handles 8 consecutive k of one row -> its 4 kp words
// share swizzle ((kp>>2)&3)<<3; STS banks = 8i + 8u2 + r : conflict-free.
// Fragment LDS swizzle is uniform per instruction -> also conflict-free.
// ---------------------------------------------------------------------------
template<int SPLITK>
__global__ void __launch_bounds__(128, 1)
gemm32_mma(const float* __restrict__ IN, const float* __restrict__ W,
           float* __restrict__ PART, int N, int K)
{
    __shared__ unsigned As[2][2][16][40];   // [buf][plane][kp][m^swz]
    __shared__ unsigned Bs[2][2][16][72];   // [buf][plane][kp][n^swz]

    const int tid  = threadIdx.x;
    const int lane = tid & 31;
    const int warp = tid >> 5;
    const int gid  = lane >> 2;   // 0..7
    const int tig  = lane & 3;    // 0..3
    const int nw   = warp * 16;   // warp's n base within the 64-wide tile

    const int n0    = blockIdx.x * 64;
    const int Ks    = K / SPLITK;
    const int kbase = blockIdx.y * Ks;
    const int nIter = Ks / 32;

    // staging map: thread -> (row, 8 consecutive k)
    const int ar  = tid >> 2;          // A row 0..31, B rows ar and ar+32
    const int u2  = tid & 3;           // k-octet index
    const int kq  = u2 * 8;            // k offset within tile
    const int kp0 = u2 * 4;            // first kp word
    const int sza = (u2 & 3) << 3;     // swizzle for this thread's kp words
    const int ca  = ar ^ sza;          // A smem column
    const int cb0 = ar ^ sza;          // B smem column, pass 0
    const int cb1 = (ar + 32) ^ sza;   // B smem column, pass 1

    float4 aR0, aR1, bR0a, bR0b, bR1a, bR1b;

#define LDG_TILE(k0)                                                          \
    {                                                                         \
        aR0  = *(const float4*)&IN[ar * K + (k0) + kq];                       \
        aR1  = *(const float4*)&IN[ar * K + (k0) + kq + 4];                   \
        bR0a = *(const float4*)&W[(size_t)(n0 + ar) * K + (k0) + kq];         \
        bR0b = *(const float4*)&W[(size_t)(n0 + ar) * K + (k0) + kq + 4];     \
        bR1a = *(const float4*)&W[(size_t)(n0 + ar + 32) * K + (k0) + kq];    \
        bR1b = *(const float4*)&W[(size_t)(n0 + ar + 32) * K + (k0) + kq + 4];\
    }

#define STS_TILE(b)                                                           \
    {                                                                         \
        unsigned h, l;                                                        \
        split2(aR0.x, aR0.y, h, l);                                           \
        As[b][0][kp0 + 0][ca] = h; As[b][1][kp0 + 0][ca] = l;                 \
        split2(aR0.z, aR0.w, h, l);                                           \
        As[b][0][kp0 + 1][ca] = h; As[b][1][kp0 + 1][ca] = l;                 \
        split2(aR1.x, aR1.y, h, l);                                           \
        As[b][0][kp0 + 2][ca] = h; As[b][1][kp0 + 2][ca] = l;                 \
        split2(aR1.z, aR1.w, h, l);                                           \
        As[b][0][kp0 + 3][ca] = h; As[b][1][kp0 + 3][ca] = l;                 \
        split2(bR0a.x, bR0a.y, h, l);                                         \
        Bs[b][0][kp0 + 0][cb0] = h; Bs[b][1][kp0 + 0][cb0] = l;               \
        split2(bR0a.z, bR0a.w, h, l);                                         \
        Bs[b][0][kp0 + 1][cb0] = h; Bs[b][1][kp0 + 1][cb0] = l;               \
        split2(bR0b.x, bR0b.y, h, l);                                         \
        Bs[b][0][kp0 + 2][cb0] = h; Bs[b][1][kp0 + 2][cb0] = l;               \
        split2(bR0b.z, bR0b.w, h, l);                                         \
        Bs[b][0][kp0 + 3][cb0] = h; Bs[b][1][kp0 + 3][cb0] = l;               \
        split2(bR1a.x, bR1a.y, h, l);                                         \
        Bs[b][0][kp0 + 0][cb1] = h; Bs[b][1][kp0 + 0][cb1] = l;               \
        split2(bR1a.z, bR1a.w, h, l);                                         \
        Bs[b][0][kp0 + 1][cb1] = h; Bs[b][1][kp0 + 1][cb1] = l;               \
        split2(bR1b.x, bR1b.y, h, l);                                         \
        Bs[b][0][kp0 + 2][cb1] = h; Bs[b][1][kp0 + 2][cb1] = l;               \
        split2(bR1b.z, bR1b.w, h, l);                                         \
        Bs[b][0][kp0 + 3][cb1] = h; Bs[b][1][kp0 + 3][cb1] = l;               \
    }

    LDG_TILE(kbase);
    STS_TILE(0);
    __syncthreads();

    float c[2][2][4] = {};

    int buf = 0;
    for (int i = 0; i < nIter; i++) {
        if (i + 1 < nIter) LDG_TILE(kbase + (i + 1) * 32);

#pragma unroll
        for (int s = 0; s < 2; s++) {
            const int kpb = s * 8;
            const int z1 = ((2 * s) & 3) << 3;       // swizzle for kp rows kpb+tig
            const int z2 = ((2 * s + 1) & 3) << 3;   // swizzle for kp rows kpb+tig+4
            unsigned ah[2][4], al[2][4];
#pragma unroll
            for (int mt = 0; mt < 2; mt++) {
                int m0 = mt * 16 + gid;
                ah[mt][0] = As[buf][0][kpb + tig][m0 ^ z1];
                ah[mt][1] = As[buf][0][kpb + tig][(m0 + 8) ^ z1];
                ah[mt][2] = As[buf][0][kpb + tig + 4][m0 ^ z2];
                ah[mt][3] = As[buf][0][kpb + tig + 4][(m0 + 8) ^ z2];
                al[mt][0] = As[buf][1][kpb + tig][m0 ^ z1];
                al[mt][1] = As[buf][1][kpb + tig][(m0 + 8) ^ z1];
                al[mt][2] = As[buf][1][kpb + tig + 4][m0 ^ z2];
                al[mt][3] = As[buf][1][kpb + tig + 4][(m0 + 8) ^ z2];
            }
#pragma unroll
            for (int t8 = 0; t8 < 2; t8++) {
                int nb = nw + t8 * 8 + gid;
                unsigned bh0 = Bs[buf][0][kpb + tig][nb ^ z1];
                unsigned bh1 = Bs[buf][0][kpb + tig + 4][nb ^ z2];
                unsigned bl0 = Bs[buf][1][kpb + tig][nb ^ z1];
                unsigned bl1 = Bs[buf][1][kpb + tig + 4][nb ^ z2];
#pragma unroll
                for (int mt = 0; mt < 2; mt++) {
                    mma_bf16(c[mt][t8], ah[mt][0], ah[mt][1], ah[mt][2], ah[mt][3], bh0, bh1);
                    mma_bf16(c[mt][t8], ah[mt][0], ah[mt][1], ah[mt][2], ah[mt][3], bl0, bl1);
                    mma_bf16(c[mt][t8], al[mt][0], al[mt][1], al[mt][2], al[mt][3], bh0, bh1);
                }
            }
        }

        if (i + 1 < nIter) STS_TILE(buf ^ 1);
        __syncthreads();
        buf ^= 1;
    }

    // write partials: c[mt][t8] -> rows mt*16+gid(+8), cols n0+nw+t8*8+2*tig
    float* base = &PART[(size_t)blockIdx.y * 32 * N];
#pragma unroll
    for (int mt = 0; mt < 2; mt++)
#pragma unroll
        for (int t8 = 0; t8 < 2; t8++) {
            int col = n0 + nw + t8 * 8 + 2 * tig;
            int r0  = mt * 16 + gid;
            *(float2*)&base[r0 * N + col]       = make_float2(c[mt][t8][0], c[mt][t8][1]);
            *(float2*)&base[(r0 + 8) * N + col] = make_float2(c[mt][t8][2], c[mt][t8][3]);
        }
#undef LDG_TILE
#undef STS_TILE
}

// ---------------------------------------------------------------------------
// block-wide sum (256 threads)
// ---------------------------------------------------------------------------
__device__ __forceinline__ float block_sum(float v, float* sh) {
#pragma unroll
    for (int o = 16; o; o >>= 1) v += __shfl_xor_sync(0xFFFFFFFFu, v, o);
    int w = threadIdx.x >> 5;
    if ((threadIdx.x & 31) == 0) sh[w] = v;
    __syncthreads();
    float r = 0.f;
    if (threadIdx.x < 32) {
        r = (threadIdx.x < 8) ? sh[threadIdx.x] : 0.f;
#pragma unroll
        for (int o = 4; o; o >>= 1) r += __shfl_xor_sync(0xFFFFFFFFu, r, o);
    }
    if (threadIdx.x == 0) sh[0] = r;
    __syncthreads();
    float out = sh[0];
    __syncthreads();
    return out;
}

// ---------------------------------------------------------------------------
// Fused split-K reduce + epilogue + LayerNorm for N=2048.
// One block per row (32 blocks, 256 threads, 8 elems/thread).
// LNMODE: 0 = write OUT_s = v only
//         1 = write OUT_s = v  and  OUT_y = LN(v)*g+b          (ln1)
//         2 = write OUT_s = LN(v)*g+b + v                      (ln2 + residual)
// ---------------------------------------------------------------------------
template<int SPLITK, int FLAGS, int LNMODE>
__global__ void reduce_ln(const float* __restrict__ PART, const float* __restrict__ bias,
                          const float* __restrict__ resid, float* __restrict__ OUT_s,
                          float* __restrict__ OUT_y, const float* __restrict__ g,
                          const float* __restrict__ bp)
{
    __shared__ float sh[8];
    const int r = blockIdx.x, tid = threadIdx.x;
    const int c0 = tid * 8;

    float o[8] = {0.f, 0.f, 0.f, 0.f, 0.f, 0.f, 0.f, 0.f};
#pragma unroll
    for (int p = 0; p < SPLITK; p++) {
        const float* b = &PART[((size_t)p * 32 + r) * Md + c0];
        float4 x0 = *(const float4*)b;
        float4 x1 = *(const float4*)(b + 4);
        o[0] += x0.x; o[1] += x0.y; o[2] += x0.z; o[3] += x0.w;
        o[4] += x1.x; o[5] += x1.y; o[6] += x1.z; o[7] += x1.w;
    }
    if (FLAGS & F_BIAS) {
        float4 b0 = *(const float4*)&bias[c0];
        float4 b1 = *(const float4*)&bias[c0 + 4];
        o[0] += b0.x; o[1] += b0.y; o[2] += b0.z; o[3] += b0.w;
        o[4] += b1.x; o[5] += b1.y; o[6] += b1.z; o[7] += b1.w;
    }
    if (FLAGS & F_SIN) {
#pragma unroll
        for (int j = 0; j < 8; j++) {
            int cc = c0 + j;
            int e = cc & ~1;
            float ang = (float)r * powf(10000.0f, -(float)e * (1.0f / 1024.0f));
            o[j] += (cc & 1) ? cosf(ang) : sinf(ang);
        }
    }
    if (FLAGS & F_RES) {
        const float* b = &resid[r * Md + c0];
        float4 x0 = *(const float4*)b;
        float4 x1 = *(const float4*)(b + 4);
        o[0] += x0.x; o[1] += x0.y; o[2] += x0.z; o[3] += x0.w;
        o[4] += x1.x; o[5] += x1.y; o[6] += x1.z; o[7] += x1.w;
    }

    if (LNMODE == 0) {
        *(float4*)&OUT_s[r * Md + c0]     = make_float4(o[0], o[1], o[2], o[3]);
        *(float4*)&OUT_s[r * Md + c0 + 4] = make_float4(o[4], o[5], o[6], o[7]);
        return;
    }

    float s = 0.f;
#pragma unroll
    for (int j = 0; j < 8; j++) s += o[j];
    float mean = block_sum(s, sh) * (1.0f / (float)Md);
    float sq = 0.f;
#pragma unroll
    for (int j = 0; j < 8; j++) { float d = o[j] - mean; sq += d * d; }
    float var = block_sum(sq, sh) * (1.0f / (float)Md);
    float rstd = rsqrtf(var + 1e-5f);

    float yv[8];
#pragma unroll
    for (int j = 0; j < 8; j++)
        yv[j] = (o[j] - mean) * rstd * g[c0 + j] + bp[c0 + j];

    if (LNMODE == 1) {
        *(float4*)&OUT_s[r * Md + c0]     = make_float4(o[0], o[1], o[2], o[3]);
        *(float4*)&OUT_s[r * Md + c0 + 4] = make_float4(o[4], o[5], o[6], o[7]);
        *(float4*)&OUT_y[r * Md + c0]     = make_float4(yv[0], yv[1], yv[2], yv[3]);
        *(float4*)&OUT_y[r * Md + c0 + 4] = make_float4(yv[4], yv[5], yv[6], yv[7]);
    } else { // LNMODE == 2
#pragma unroll
        for (int j = 0; j < 8; j++) yv[j] += o[j];
        *(float4*)&OUT_s[r * Md + c0]     = make_float4(yv[0], yv[1], yv[2], yv[3]);
        *(float4*)&OUT_s[r * Md + c0 + 4] = make_float4(yv[4], yv[5], yv[6], yv[7]);
    }
}

// ---------------------------------------------------------------------------
// Elementwise split-K reduction (for N=6144 / N=8192) + optional bias/gelu
// ---------------------------------------------------------------------------
template<int SPLITK, int FLAGS>
__global__ void reduce_ep(const float* __restrict__ PART, const float* __restrict__ bias,
                          float* __restrict__ OUT, int N)
{
    int idx = blockIdx.x * blockDim.x + threadIdx.x;
    int n4 = N >> 2;
    if (idx >= 32 * n4) return;
    int r = idx / n4;
    int c = (idx - r * n4) * 4;

    float o[4] = {0.f, 0.f, 0.f, 0.f};
#pragma unroll
    for (int p = 0; p < SPLITK; p++) {
        float4 v = *(const float4*)&PART[((size_t)p * 32 + r) * N + c];
        o[0] += v.x; o[1] += v.y; o[2] += v.z; o[3] += v.w;
    }
    if (FLAGS & F_BIAS) {
        float4 b = *(const float4*)&bias[c];
        o[0] += b.x; o[1] += b.y; o[2] += b.z; o[3] += b.w;
    }
    if (FLAGS & F_GELU) {
#pragma unroll
        for (int j = 0; j < 4; j++)
            o[j] = 0.5f * o[j] * (1.0f + erff(o[j] * 0.70710678118654752f));
    }
    *(float4*)&OUT[r * N + c] = make_float4(o[0], o[1], o[2], o[3]);
}

// ---------------------------------------------------------------------------
// Scalar attention + serial cumsum.
// Phase 1: warp-per-token rsa (no block syncs). Phase 2: sync-free cumsum
// loop -> all 32 v-loads pipeline (deep MLP) behind the serial FADD chain.
// ---------------------------------------------------------------------------
__global__ void attn_kernel(const float* __restrict__ qkv, float* __restrict__ imv) {
    __shared__ float srsa[AVGF];
    int h = blockIdx.x, tid = threadIdx.x;
    int lane = tid & 31, warp = tid >> 5;
    const float inv = 0.088388347648318447f; // 1/sqrt(128)

    // phase 1: rsa[i] for i = 4*ii + warp
#pragma unroll
    for (int ii = 0; ii < 8; ii++) {
        int i = ii * 4 + warp;
        const float* qp = qkv + i * (3 * Md) + h * DHd;
        float p = 0.f;
#pragma unroll
        for (int j = 0; j < 4; j++) {
            float q = qp[lane + 32 * j];
            float k = qp[Md + lane + 32 * j];
            p = fmaf(q, k, p);
        }
#pragma unroll
        for (int o = 16; o; o >>= 1) p += __shfl_xor_sync(0xFFFFFFFFu, p, o);
        if (lane == 0) srsa[i] = p * inv;
    }
    __syncthreads();

    // phase 2: serial cumsum over tokens (no syncs in loop)
    int d = tid;   // 0..127
    float run = 0.f;
#pragma unroll
    for (int i = 0; i < AVGF; i++) {
        run = fmaf(srsa[i], qkv[i * (3 * Md) + 2 * Md + h * DHd + d], run);
        imv[i * Md + h * DHd + d] = run;
    }
}

// ---------------------------------------------------------------------------
// launch
// ---------------------------------------------------------------------------
extern "C" void kernel_launch(void* const* d_in, const int* in_sizes, int n_in,
                              void* d_out, int out_size) {
    const float* x      = (const float*)d_in[0];
    const float* weight = (const float*)d_in[1];
    const float* Wqkv   = (const float*)d_in[2];
    const float* Wo     = (const float*)d_in[3];
    const float* ln1_g  = (const float*)d_in[4];
    const float* ln1_b  = (const float*)d_in[5];
    const float* ln2_g  = (const float*)d_in[6];
    const float* ln2_b  = (const float*)d_in[7];
    const float* fc1_w  = (const float*)d_in[8];
    const float* fc1_b  = (const float*)d_in[9];
    const float* fc2_w  = (const float*)d_in[10];
    const float* fc2_b  = (const float*)d_in[11];
    float* out = (float*)d_out;

    float *altx, *s, *y, *qkv, *imv, *hbuf, *part;
    cudaGetSymbolAddress((void**)&altx, g_altx);
    cudaGetSymbolAddress((void**)&s,    g_s);
    cudaGetSymbolAddress((void**)&y,    g_y);
    cudaGetSymbolAddress((void**)&qkv,  g_qkv);
    cudaGetSymbolAddress((void**)&imv,  g_imv);
    cudaGetSymbolAddress((void**)&hbuf, g_h);
    cudaGetSymbolAddress((void**)&part, g_part);

    auto rgrid = [](int N) { return (32 * (N / 4) + 127) / 128; };

    // 1) segment average
    avg_kernel<<<C2d * C1d, 256>>>(x, altx);

    // 2) s = altx @ weight^T + sin bias; y = LN1(s)   (N=2048, K=2048, splitK=16)
    gemm32_mma<16><<<dim3(Md / 64, 16), 128>>>(altx, weight, part, Md, Md);
    reduce_ln<16, F_SIN, 1><<<AVGF, 256>>>(part, nullptr, nullptr, s, y, ln1_g, ln1_b);

    for (int a = 0; a < TKd; a++) {
        // qkv = y @ Wqkv[a]^T      (N=6144, K=2048, splitK=8 -> 768 blocks)
        gemm32_mma<8><<<dim3((3 * Md) / 64, 8), 128>>>(
            y, Wqkv + (size_t)a * 3 * Md * Md, part, 3 * Md, Md);
        reduce_ep<8, 0><<<rgrid(3 * Md), 128>>>(part, nullptr, qkv, 3 * Md);

        // scalar attention + cumsum
        attn_kernel<<<HAd, DHd>>>(qkv, imv);

        // s' = imv @ Wo[a]^T + s;  s = LN2(s') + s'   (N=2048, K=2048, splitK=16)
        gemm32_mma<16><<<dim3(Md / 64, 16), 128>>>(
            imv, Wo + (size_t)a * Md * Md, part, Md, Md);
        reduce_ln<16, F_RES, 2><<<AVGF, 256>>>(part, nullptr, s, s, nullptr, ln2_g, ln2_b);

        // h = gelu(s @ fc1^T + b)  (N=8192, K=2048, splitK=8 -> 1024 blocks)
        gemm32_mma<8><<<dim3((4 * Md) / 64, 8), 128>>>(s, fc1_w, part, 4 * Md, Md);
        reduce_ep<8, F_BIAS | F_GELU><<<rgrid(4 * Md), 128>>>(part, fc1_b, hbuf, 4 * Md);

        // s = h @ fc2^T + b        (N=2048, K=8192, splitK=16 -> 512 blocks)
        gemm32_mma<16><<<dim3(Md / 64, 16), 128>>>(hbuf, fc2_w, part, Md, 4 * Md);
        if (a < TKd - 1) {
            // fuse next block's LN1: write s and y
            reduce_ln<16, F_BIAS, 1><<<AVGF, 256>>>(part, fc2_b, nullptr, s, y,
                                                    ln1_g, ln1_b);
        } else {
            reduce_ln<16, F_BIAS, 0><<<AVGF, 256>>>(part, fc2_b, nullptr, out, nullptr,
                                                    nullptr, nullptr);
        }
    }
}